// round 4
// baseline (speedup 1.0000x reference)
#include <cuda_runtime.h>
#include <cuda_fp16.h>
#include <cstdint>

#define NS     25
#define NQ     200
#define NITEM  (NS + NQ)        // 225
#define FF     80
#define DD     512
#define WAY    5
#define BLK    128
#define NBLK   10               // packed upper-tri 128x128 blocks of 4x4 grid
#define BLKSZ  (BLK * BLK)      // 16384
#define KPACK  (NBLK * BLKSZ)   // 163840
#define PITCH  136              // smem pitch (halves) for X slices
#define CPITCH 136              // smem pitch (halves) for C staging (16B-aligned rows)

// -------- scratch (__device__ globals; no allocations allowed) --------------
__device__ __half g_Sn[NS * FF * DD];        // 2 MB   normalized supports
__device__ __half g_Qn[NQ * FF * DD];        // 16.4MB normalized queries
__device__ float  g_bar[NITEM][DD];          // per-item feature-row sums
__device__ float  g_sbarsum[WAY][DD];        // class-summed support row-sums
__device__ int    g_cls_cnt[WAY];
__device__ int    g_cls_sup[WAY][NS];
__device__ __half g_Gp[WAY][KPACK];          // packed class Grams (x2 off-diag)
__device__ __half g_Hp[NQ][KPACK];           // packed query Grams
__device__ float  g_S2[WAY][NQ];

__constant__ int c_bi[NBLK] = {0,0,0,0,1,1,1,2,2,3};
__constant__ int c_bj[NBLK] = {0,1,2,3,1,2,3,2,3,3};

// ---------------------------------------------------------------------------
// K1: L2-normalize each D=512 feature row, gather global/local concat, fp16.
// One warp per row. (proven, 10.7us)
// ---------------------------------------------------------------------------
__global__ void normalize_kernel(const float* __restrict__ sg, const float* __restrict__ sl,
                                 const float* __restrict__ qg, const float* __restrict__ ql)
{
    int warp = (blockIdx.x * blockDim.x + threadIdx.x) >> 5;
    int lane = threadIdx.x & 31;
    if (warp >= NITEM * FF) return;

    const float* src;
    __half* dst;
    if (warp < NS * FF) {
        int s = warp / FF, f = warp % FF;
        src = (f < 16) ? sg + (size_t)(s * 16 + f) * DD
                       : sl + (size_t)(s * 64 + (f - 16)) * DD;
        dst = g_Sn + (size_t)warp * DD;
    } else {
        int r = warp - NS * FF;
        int q = r / FF, f = r % FF;
        src = (f < 16) ? qg + (size_t)(q * 16 + f) * DD
                       : ql + (size_t)(q * 64 + (f - 16)) * DD;
        dst = g_Qn + (size_t)r * DD;
    }

    float4 v[4];
    float ss = 0.f;
    const float4* s4 = reinterpret_cast<const float4*>(src);
#pragma unroll
    for (int i = 0; i < 4; i++) {
        v[i] = s4[lane + 32 * i];
        ss += v[i].x * v[i].x + v[i].y * v[i].y + v[i].z * v[i].z + v[i].w * v[i].w;
    }
#pragma unroll
    for (int o = 16; o; o >>= 1) ss += __shfl_xor_sync(0xFFFFFFFFu, ss, o);
    float rn = rsqrtf(fmaxf(ss, 1e-24f));

    __half2* d2 = reinterpret_cast<__half2*>(dst);
#pragma unroll
    for (int i = 0; i < 4; i++) {
        d2[2 * (lane + 32 * i) + 0] = __floats2half2_rn(v[i].x * rn, v[i].y * rn);
        d2[2 * (lane + 32 * i) + 1] = __floats2half2_rn(v[i].z * rn, v[i].w * rn);
    }
}

// ---------------------------------------------------------------------------
// K2: per-item feature-row sums
// ---------------------------------------------------------------------------
__global__ void rowsum_kernel()
{
    int item = blockIdx.x;
    int t = threadIdx.x;  // 256 threads, 2 cols each
    const __half2* X = reinterpret_cast<const __half2*>(
        (item < NS) ? g_Sn + (size_t)item * FF * DD
                    : g_Qn + (size_t)(item - NS) * FF * DD);
    float sx = 0.f, sy = 0.f;
#pragma unroll 8
    for (int f = 0; f < FF; f++) {
        float2 v = __half22float2(X[f * (DD / 2) + t]);
        sx += v.x; sy += v.y;
    }
    g_bar[item][2 * t + 0] = sx;
    g_bar[item][2 * t + 1] = sy;
}

// ---------------------------------------------------------------------------
// K3: class lists, class-summed row-sums, zero S2
// ---------------------------------------------------------------------------
__global__ void prep_kernel(const long long* __restrict__ labels)
{
    __shared__ int cnt[WAY];
    __shared__ int sup[WAY][NS];
    int t = threadIdx.x;  // 512
    if (t == 0) {
        for (int c = 0; c < WAY; c++) cnt[c] = 0;
        for (int s = 0; s < NS; s++) {
            int c = (int)labels[s];
            sup[c][cnt[c]++] = s;
        }
        for (int c = 0; c < WAY; c++) {
            g_cls_cnt[c] = cnt[c];
            for (int i = 0; i < cnt[c]; i++) g_cls_sup[c][i] = sup[c][i];
        }
    }
    __syncthreads();
    if (t < DD) {
#pragma unroll
        for (int c = 0; c < WAY; c++) {
            float a = 0.f;
            for (int i = 0; i < cnt[c]; i++) a += g_bar[sup[c][i]][t];
            g_sbarsum[c][t] = a;
        }
    }
    for (int i = t; i < WAY * NQ; i += blockDim.x)
        (&g_S2[0][0])[i] = 0.f;
}

// ---------------------------------------------------------------------------
// K4: packed Gram blocks (Round-2 structure + smem-staged coalesced epilogue)
// ---------------------------------------------------------------------------
__device__ __forceinline__ void ldsm_x4_t(uint32_t (&r)[4], const __half* p)
{
    uint32_t a = (uint32_t)__cvta_generic_to_shared(p);
    asm volatile("ldmatrix.sync.aligned.m8n8.x4.trans.shared.b16 {%0,%1,%2,%3}, [%4];"
                 : "=r"(r[0]), "=r"(r[1]), "=r"(r[2]), "=r"(r[3]) : "r"(a));
}

__device__ __forceinline__ void mma16816(float (&d)[4], const uint32_t (&a)[4],
                                         uint32_t b0, uint32_t b1)
{
    asm volatile("mma.sync.aligned.m16n8k16.row.col.f32.f16.f16.f32 "
                 "{%0,%1,%2,%3},{%4,%5,%6,%7},{%8,%9},{%0,%1,%2,%3};"
                 : "+f"(d[0]), "+f"(d[1]), "+f"(d[2]), "+f"(d[3])
                 : "r"(a[0]), "r"(a[1]), "r"(a[2]), "r"(a[3]), "r"(b0), "r"(b1));
}

extern __shared__ char dynsmem[];

__global__ void __launch_bounds__(256) gram_kernel()
{
    __half* sX0 = (__half*)dynsmem;                          // 80 x PITCH
    __half* sX1 = sX0 + FF * PITCH;                          // 80 x PITCH
    __half* sC  = sX1 + FF * PITCH;                          // 128 x CPITCH

    const int b    = blockIdx.x;
    const int item = blockIdx.y;
    const int bi = c_bi[b], bj = c_bj[b];
    const bool diag = (bi == bj);

    const int tid  = threadIdx.x;
    const int lane = tid & 31;
    const int warp = tid >> 5;
    const int m_base = (warp >> 1) * 32;
    const int n_base = (warp & 1) * 64;

    float acc[2][8][4];
#pragma unroll
    for (int mt = 0; mt < 2; mt++)
#pragma unroll
        for (int nt = 0; nt < 8; nt++)
#pragma unroll
            for (int i = 0; i < 4; i++) acc[mt][nt][i] = 0.f;

    const int nsup = (item < WAY) ? g_cls_cnt[item] : 1;
    const __half* pB = diag ? sX0 : sX1;
    const int nch = diag ? 1280 : 2560;

    const int a_krow = ((lane >> 4) << 3) + (lane & 7);
    const int a_coff = ((lane >> 3) & 1) << 3;
    const int b_krow = (((lane >> 3) & 1) << 3) + (lane & 7);
    const int b_coff = (lane >> 4) << 3;

    for (int si = 0; si < nsup; si++) {
        const __half* base = (item < WAY)
            ? g_Sn + (size_t)g_cls_sup[item][si] * FF * DD
            : g_Qn + (size_t)(item - WAY) * FF * DD;

        for (int ch = tid; ch < nch; ch += 256) {
            int tile = (ch >= 1280) ? 1 : 0;
            int rem  = ch - tile * 1280;
            int r = rem >> 4, cc = rem & 15;
            int colblk = tile ? bj : bi;
            const __half* src = base + (size_t)r * DD + colblk * 128 + cc * 8;
            __half* dsts = (tile ? sX1 : sX0) + r * PITCH + cc * 8;
            uint32_t dst = (uint32_t)__cvta_generic_to_shared(dsts);
            asm volatile("cp.async.cg.shared.global [%0], [%1], 16;" :: "r"(dst), "l"(src));
        }
        asm volatile("cp.async.commit_group;");
        asm volatile("cp.async.wait_group 0;");
        __syncthreads();

#pragma unroll
        for (int k16 = 0; k16 < FF / 16; k16++) {
            const int k0 = k16 * 16;
            uint32_t a[2][4];
#pragma unroll
            for (int mt = 0; mt < 2; mt++)
                ldsm_x4_t(a[mt], &sX0[(k0 + a_krow) * PITCH + m_base + mt * 16 + a_coff]);
#pragma unroll
            for (int nt = 0; nt < 4; nt++) {
                uint32_t bf[4];
                ldsm_x4_t(bf, &pB[(k0 + b_krow) * PITCH + n_base + nt * 16 + b_coff]);
#pragma unroll
                for (int mt = 0; mt < 2; mt++) {
                    mma16816(acc[mt][2 * nt + 0], a[mt], bf[0], bf[1]);
                    mma16816(acc[mt][2 * nt + 1], a[mt], bf[2], bf[3]);
                }
            }
        }
        __syncthreads();
    }

    // ---- epilogue: stage to smem (fragment scatter), then coalesced int4 out
    const float scale = (item < WAY && !diag) ? 2.f : 1.f;
#pragma unroll
    for (int mt = 0; mt < 2; mt++) {
        int r = m_base + mt * 16 + (lane >> 2);
#pragma unroll
        for (int nt = 0; nt < 8; nt++) {
            int c = n_base + nt * 8 + (lane & 3) * 2;
            *(__half2*)(sC + r * CPITCH + c) =
                __floats2half2_rn(acc[mt][nt][0] * scale, acc[mt][nt][1] * scale);
            *(__half2*)(sC + (r + 8) * CPITCH + c) =
                __floats2half2_rn(acc[mt][nt][2] * scale, acc[mt][nt][3] * scale);
        }
    }
    __syncthreads();

    __half* out = ((item < WAY) ? g_Gp[item] : g_Hp[item - WAY]) + b * BLKSZ;
#pragma unroll
    for (int idx = tid; idx < 2048; idx += 256) {          // 2048 int4 = 32KB
        int row = idx >> 4, col8 = idx & 15;
        *(int4*)(out + row * BLK + col8 * 8) = *(const int4*)(sC + row * CPITCH + col8 * 8);
    }
}

// ---------------------------------------------------------------------------
// K5 (dot-v3): S2[c][q] = <Gp[c], Hp[q]>. CTA = (k-chunk of 4096, 50-query
// group). Each thread owns 16 k-halves; G slice cached in registers (reused
// 50x); H streamed coalesced; warp butterfly + REDG atomics.
// ---------------------------------------------------------------------------
__global__ void __launch_bounds__(256) dot_kernel()
{
    const int kc   = blockIdx.x;            // 0..39
    const int qg   = blockIdx.y;            // 0..3
    const int lane = threadIdx.x & 31;
    const int warp = threadIdx.x >> 5;
    const int kbase = kc * 4096 + warp * 512 + lane * 8;   // halves

    __half2 G[WAY][8];
#pragma unroll
    for (int c = 0; c < WAY; c++) {
        *(int4*)&G[c][0] = *(const int4*)&g_Gp[c][kbase];
        *(int4*)&G[c][4] = *(const int4*)&g_Gp[c][kbase + 256];
    }

    for (int qi = 0; qi < 50; qi++) {
        const int q = qg * 50 + qi;
        __half2 H[8];
        *(int4*)&H[0] = *(const int4*)&g_Hp[q][kbase];
        *(int4*)&H[4] = *(const int4*)&g_Hp[q][kbase + 256];

        float p0, p1, p2, p3, p4;
        {
            __half2 a0 = __hmul2(G[0][0], H[0]);
            __half2 a1 = __hmul2(G[1][0], H[0]);
            __half2 a2 = __hmul2(G[2][0], H[0]);
            __half2 a3 = __hmul2(G[3][0], H[0]);
            __half2 a4 = __hmul2(G[4][0], H[0]);
#pragma unroll
            for (int j = 1; j < 8; j++) {
                a0 = __hfma2(G[0][j], H[j], a0);
                a1 = __hfma2(G[1][j], H[j], a1);
                a2 = __hfma2(G[2][j], H[j], a2);
                a3 = __hfma2(G[3][j], H[j], a3);
                a4 = __hfma2(G[4][j], H[j], a4);
            }
            float2 f;
            f = __half22float2(a0); p0 = f.x + f.y;
            f = __half22float2(a1); p1 = f.x + f.y;
            f = __half22float2(a2); p2 = f.x + f.y;
            f = __half22float2(a3); p3 = f.x + f.y;
            f = __half22float2(a4); p4 = f.x + f.y;
        }
#pragma unroll
        for (int o = 16; o; o >>= 1) {
            p0 += __shfl_xor_sync(0xFFFFFFFFu, p0, o);
            p1 += __shfl_xor_sync(0xFFFFFFFFu, p1, o);
            p2 += __shfl_xor_sync(0xFFFFFFFFu, p2, o);
            p3 += __shfl_xor_sync(0xFFFFFFFFu, p3, o);
            p4 += __shfl_xor_sync(0xFFFFFFFFu, p4, o);
        }
        if (lane == 0) {
            atomicAdd(&g_S2[0][q], p0);
            atomicAdd(&g_S2[1][q], p1);
            atomicAdd(&g_S2[2][q], p2);
            atomicAdd(&g_S2[3][q], p3);
            atomicAdd(&g_S2[4][q], p4);
        }
    }
}

// ---------------------------------------------------------------------------
// K6: logits[q][c] = -2*F^2 + (4*S1 - 2*S2)/cnt. One warp per query.
// ---------------------------------------------------------------------------
__global__ void logits_kernel(float* __restrict__ out)
{
    int warp = (blockIdx.x * blockDim.x + threadIdx.x) >> 5;
    int lane = threadIdx.x & 31;
    if (warp >= NQ) return;
    const int q = warp;

    float s1[WAY] = {0.f, 0.f, 0.f, 0.f, 0.f};
    const float* qb = g_bar[NS + q];
    for (int k = lane; k < DD; k += 32) {
        float qv = qb[k];
#pragma unroll
        for (int c = 0; c < WAY; c++) s1[c] += g_sbarsum[c][k] * qv;
    }
#pragma unroll
    for (int o = 16; o; o >>= 1)
#pragma unroll
        for (int c = 0; c < WAY; c++)
            s1[c] += __shfl_xor_sync(0xFFFFFFFFu, s1[c], o);

    if (lane < WAY) {
        int c = lane;
        float cnt = (float)g_cls_cnt[c];
        out[q * WAY + c] = -2.f * (float)(FF * FF) + (4.f * s1[c] - 2.f * g_S2[c][q]) / cnt;
    }
}

// ---------------------------------------------------------------------------
extern "C" void kernel_launch(void* const* d_in, const int* in_sizes, int n_in,
                              void* d_out, int out_size)
{
    const float*     sg  = (const float*)d_in[0];
    const float*     sl  = (const float*)d_in[1];
    const long long* lab = (const long long*)d_in[2];
    const float*     qg  = (const float*)d_in[3];
    const float*     ql  = (const float*)d_in[4];
    float*           out = (float*)d_out;

    const int smem = (2 * FF * PITCH + BLK * CPITCH) * 2 + 64;   // ~78.5 KB
    static bool attr_set = false;
    if (!attr_set) {
        cudaFuncSetAttribute(gram_kernel, cudaFuncAttributeMaxDynamicSharedMemorySize, smem);
        attr_set = true;
    }

    const int rows = NITEM * FF;
    normalize_kernel<<<(rows * 32 + 255) / 256, 256>>>(sg, sl, qg, ql);
    rowsum_kernel<<<NITEM, 256>>>();
    prep_kernel<<<1, 512>>>(lab);
    gram_kernel<<<dim3(NBLK, WAY + NQ), 256, smem>>>();   // 2050 CTAs
    dot_kernel<<<dim3(40, 4), 256>>>();                   // 160 CTAs
    logits_kernel<<<(NQ * 32 + 255) / 256, 256>>>(out);
}

// round 5
// speedup vs baseline: 1.4206x; 1.4206x over previous
#include <cuda_runtime.h>
#include <cuda_fp16.h>
#include <cstdint>

#define NS     25
#define NQ     200
#define NITEM  (NS + NQ)        // 225
#define FF     80
#define DD     512
#define WAY    5
#define BLK    128
#define NBLK   10               // packed upper-tri 128x128 blocks of 4x4 grid
#define BLKSZ  (BLK * BLK)      // 16384
#define KPACK  (NBLK * BLKSZ)   // 163840
#define PITCH  136              // smem pitch (halves) for X slices
#define CPITCH 136              // smem pitch (halves) for C staging

// -------- scratch (__device__ globals; no allocations allowed) --------------
__device__ __half g_Sn[NS * FF * DD];        // 2 MB   normalized supports
__device__ __half g_Qn[NQ * FF * DD];        // 16.4MB normalized queries
__device__ float  g_bar[NITEM][DD];          // per-item feature-row sums
__device__ float  g_sbarsum[WAY][DD];        // class-summed support row-sums
__device__ int    g_cls_cnt[WAY];
__device__ int    g_cls_sup[WAY][NS];
__device__ __half g_Gp[WAY][KPACK];          // packed class Grams (x2 off-diag)
__device__ __half g_Hp[NQ][KPACK];           // packed query Grams
__device__ float  g_S2[WAY][NQ];

__constant__ int c_bi[NBLK] = {0,0,0,0,1,1,1,2,2,3};
__constant__ int c_bj[NBLK] = {0,1,2,3,1,2,3,2,3,3};

// ---------------------------------------------------------------------------
// K1: L2-normalize each D=512 feature row (proven)
// ---------------------------------------------------------------------------
__global__ void normalize_kernel(const float* __restrict__ sg, const float* __restrict__ sl,
                                 const float* __restrict__ qg, const float* __restrict__ ql)
{
    int warp = (blockIdx.x * blockDim.x + threadIdx.x) >> 5;
    int lane = threadIdx.x & 31;
    if (warp >= NITEM * FF) return;

    const float* src;
    __half* dst;
    if (warp < NS * FF) {
        int s = warp / FF, f = warp % FF;
        src = (f < 16) ? sg + (size_t)(s * 16 + f) * DD
                       : sl + (size_t)(s * 64 + (f - 16)) * DD;
        dst = g_Sn + (size_t)warp * DD;
    } else {
        int r = warp - NS * FF;
        int q = r / FF, f = r % FF;
        src = (f < 16) ? qg + (size_t)(q * 16 + f) * DD
                       : ql + (size_t)(q * 64 + (f - 16)) * DD;
        dst = g_Qn + (size_t)r * DD;
    }

    float4 v[4];
    float ss = 0.f;
    const float4* s4 = reinterpret_cast<const float4*>(src);
#pragma unroll
    for (int i = 0; i < 4; i++) {
        v[i] = s4[lane + 32 * i];
        ss += v[i].x * v[i].x + v[i].y * v[i].y + v[i].z * v[i].z + v[i].w * v[i].w;
    }
#pragma unroll
    for (int o = 16; o; o >>= 1) ss += __shfl_xor_sync(0xFFFFFFFFu, ss, o);
    float rn = rsqrtf(fmaxf(ss, 1e-24f));

    __half2* d2 = reinterpret_cast<__half2*>(dst);
#pragma unroll
    for (int i = 0; i < 4; i++) {
        d2[2 * (lane + 32 * i) + 0] = __floats2half2_rn(v[i].x * rn, v[i].y * rn);
        d2[2 * (lane + 32 * i) + 1] = __floats2half2_rn(v[i].z * rn, v[i].w * rn);
    }
}

// ---------------------------------------------------------------------------
// K2: per-item feature-row sums (proven)
// ---------------------------------------------------------------------------
__global__ void rowsum_kernel()
{
    int item = blockIdx.x;
    int t = threadIdx.x;
    const __half2* X = reinterpret_cast<const __half2*>(
        (item < NS) ? g_Sn + (size_t)item * FF * DD
                    : g_Qn + (size_t)(item - NS) * FF * DD);
    float sx = 0.f, sy = 0.f;
#pragma unroll 8
    for (int f = 0; f < FF; f++) {
        float2 v = __half22float2(X[f * (DD / 2) + t]);
        sx += v.x; sy += v.y;
    }
    g_bar[item][2 * t + 0] = sx;
    g_bar[item][2 * t + 1] = sy;
}

// ---------------------------------------------------------------------------
// K3: class lists, class-summed row-sums, zero S2 (proven)
// ---------------------------------------------------------------------------
__global__ void prep_kernel(const long long* __restrict__ labels)
{
    __shared__ int cnt[WAY];
    __shared__ int sup[WAY][NS];
    int t = threadIdx.x;  // 512
    if (t == 0) {
        for (int c = 0; c < WAY; c++) cnt[c] = 0;
        for (int s = 0; s < NS; s++) {
            int c = (int)labels[s];
            sup[c][cnt[c]++] = s;
        }
        for (int c = 0; c < WAY; c++) {
            g_cls_cnt[c] = cnt[c];
            for (int i = 0; i < cnt[c]; i++) g_cls_sup[c][i] = sup[c][i];
        }
    }
    __syncthreads();
    if (t < DD) {
#pragma unroll
        for (int c = 0; c < WAY; c++) {
            float a = 0.f;
            for (int i = 0; i < cnt[c]; i++) a += g_bar[sup[c][i]][t];
            g_sbarsum[c][t] = a;
        }
    }
    for (int i = t; i < WAY * NQ; i += blockDim.x)
        (&g_S2[0][0])[i] = 0.f;
}

// ---------------------------------------------------------------------------
// K4: packed Gram blocks; C staging aliases X buffers -> 43.5KB smem, 2 CTAs/SM
// ---------------------------------------------------------------------------
__device__ __forceinline__ void ldsm_x4_t(uint32_t (&r)[4], const __half* p)
{
    uint32_t a = (uint32_t)__cvta_generic_to_shared(p);
    asm volatile("ldmatrix.sync.aligned.m8n8.x4.trans.shared.b16 {%0,%1,%2,%3}, [%4];"
                 : "=r"(r[0]), "=r"(r[1]), "=r"(r[2]), "=r"(r[3]) : "r"(a));
}

__device__ __forceinline__ void mma16816(float (&d)[4], const uint32_t (&a)[4],
                                         uint32_t b0, uint32_t b1)
{
    asm volatile("mma.sync.aligned.m16n8k16.row.col.f32.f16.f16.f32 "
                 "{%0,%1,%2,%3},{%4,%5,%6,%7},{%8,%9},{%0,%1,%2,%3};"
                 : "+f"(d[0]), "+f"(d[1]), "+f"(d[2]), "+f"(d[3])
                 : "r"(a[0]), "r"(a[1]), "r"(a[2]), "r"(a[3]), "r"(b0), "r"(b1));
}

extern __shared__ char dynsmem[];

__global__ void __launch_bounds__(256, 2) gram_kernel()
{
    __half* sX0 = (__half*)dynsmem;                // 80 x PITCH
    __half* sX1 = sX0 + FF * PITCH;                // 80 x PITCH
    __half* sC  = sX0;                             // ALIAS: used only after mma phase

    const int b    = blockIdx.x;
    const int item = blockIdx.y;
    const int bi = c_bi[b], bj = c_bj[b];
    const bool diag = (bi == bj);

    const int tid  = threadIdx.x;
    const int lane = tid & 31;
    const int warp = tid >> 5;
    const int m_base = (warp >> 1) * 32;
    const int n_base = (warp & 1) * 64;

    float acc[2][8][4];
#pragma unroll
    for (int mt = 0; mt < 2; mt++)
#pragma unroll
        for (int nt = 0; nt < 8; nt++)
#pragma unroll
            for (int i = 0; i < 4; i++) acc[mt][nt][i] = 0.f;

    const int nsup = (item < WAY) ? g_cls_cnt[item] : 1;
    const __half* pB = diag ? sX0 : sX1;
    const int nch = diag ? 1280 : 2560;

    const int a_krow = ((lane >> 4) << 3) + (lane & 7);
    const int a_coff = ((lane >> 3) & 1) << 3;
    const int b_krow = (((lane >> 3) & 1) << 3) + (lane & 7);
    const int b_coff = (lane >> 4) << 3;

    for (int si = 0; si < nsup; si++) {
        const __half* base = (item < WAY)
            ? g_Sn + (size_t)g_cls_sup[item][si] * FF * DD
            : g_Qn + (size_t)(item - WAY) * FF * DD;

        for (int ch = tid; ch < nch; ch += 256) {
            int tile = (ch >= 1280) ? 1 : 0;
            int rem  = ch - tile * 1280;
            int r = rem >> 4, cc = rem & 15;
            int colblk = tile ? bj : bi;
            const __half* src = base + (size_t)r * DD + colblk * 128 + cc * 8;
            __half* dsts = (tile ? sX1 : sX0) + r * PITCH + cc * 8;
            uint32_t dst = (uint32_t)__cvta_generic_to_shared(dsts);
            asm volatile("cp.async.cg.shared.global [%0], [%1], 16;" :: "r"(dst), "l"(src));
        }
        asm volatile("cp.async.commit_group;");
        asm volatile("cp.async.wait_group 0;");
        __syncthreads();

#pragma unroll
        for (int k16 = 0; k16 < FF / 16; k16++) {
            const int k0 = k16 * 16;
            uint32_t a[2][4];
#pragma unroll
            for (int mt = 0; mt < 2; mt++)
                ldsm_x4_t(a[mt], &sX0[(k0 + a_krow) * PITCH + m_base + mt * 16 + a_coff]);
#pragma unroll
            for (int nt = 0; nt < 4; nt++) {
                uint32_t bf[4];
                ldsm_x4_t(bf, &pB[(k0 + b_krow) * PITCH + n_base + nt * 16 + b_coff]);
#pragma unroll
                for (int mt = 0; mt < 2; mt++) {
                    mma16816(acc[mt][2 * nt + 0], a[mt], bf[0], bf[1]);
                    mma16816(acc[mt][2 * nt + 1], a[mt], bf[2], bf[3]);
                }
            }
        }
        __syncthreads();   // also protects sC alias below on last iteration
    }

    // ---- epilogue: stage to aliased smem, then coalesced int4 out ----
    const float scale = (item < WAY && !diag) ? 2.f : 1.f;
#pragma unroll
    for (int mt = 0; mt < 2; mt++) {
        int r = m_base + mt * 16 + (lane >> 2);
#pragma unroll
        for (int nt = 0; nt < 8; nt++) {
            int c = n_base + nt * 8 + (lane & 3) * 2;
            *(__half2*)(sC + r * CPITCH + c) =
                __floats2half2_rn(acc[mt][nt][0] * scale, acc[mt][nt][1] * scale);
            *(__half2*)(sC + (r + 8) * CPITCH + c) =
                __floats2half2_rn(acc[mt][nt][2] * scale, acc[mt][nt][3] * scale);
        }
    }
    __syncthreads();

    __half* out = ((item < WAY) ? g_Gp[item] : g_Hp[item - WAY]) + b * BLKSZ;
#pragma unroll
    for (int idx = tid; idx < 2048; idx += 256) {
        int row = idx >> 4, col8 = idx & 15;
        *(int4*)(out + row * BLK + col8 * 8) = *(const int4*)(sC + row * CPITCH + col8 * 8);
    }
}

// ---------------------------------------------------------------------------
// K5 (dot-v5): grid (40 kchunks x 25 query-octets) = 1000 CTAs. Per thread:
// G slice (5 classes x 16 halves) in REGISTERS, stream 8 queries' H coalesced,
// fp32 accumulate, batched butterfly, block reduce, 40 atomics per CTA.
// ---------------------------------------------------------------------------
__global__ void __launch_bounds__(256) dot_kernel()
{
    const int kc   = blockIdx.x;            // 0..39
    const int q0   = blockIdx.y * 8;        // 0..192
    const int tid  = threadIdx.x;
    const int lane = tid & 31;
    const int warp = tid >> 5;
    const int kbase = kc * 4096 + tid * 16; // halves

    __half2 G[WAY][8];
#pragma unroll
    for (int c = 0; c < WAY; c++) {
        *(int4*)&G[c][0] = *(const int4*)&g_Gp[c][kbase];
        *(int4*)&G[c][4] = *(const int4*)&g_Gp[c][kbase + 8];
    }

    float acc[8][WAY];
#pragma unroll
    for (int qi = 0; qi < 8; qi++)
#pragma unroll
        for (int c = 0; c < WAY; c++) acc[qi][c] = 0.f;

#pragma unroll
    for (int qi = 0; qi < 8; qi++) {
        const __half* Hq = g_Hp[q0 + qi] + kbase;
        __half2 H[8];
        *(int4*)&H[0] = *(const int4*)(Hq);
        *(int4*)&H[4] = *(const int4*)(Hq + 8);
#pragma unroll
        for (int c = 0; c < WAY; c++) {
            __half2 a = __hmul2(G[c][0], H[0]);
#pragma unroll
            for (int j = 1; j < 8; j++) a = __hfma2(G[c][j], H[j], a);
            float2 f = __half22float2(a);
            acc[qi][c] = f.x + f.y;
        }
    }

    // batched warp butterfly over all 40 partials (independent chains)
#pragma unroll
    for (int o = 16; o; o >>= 1)
#pragma unroll
        for (int qi = 0; qi < 8; qi++)
#pragma unroll
            for (int c = 0; c < WAY; c++)
                acc[qi][c] += __shfl_xor_sync(0xFFFFFFFFu, acc[qi][c], o);

    __shared__ float red[8][8][WAY];
    if (lane == 0)
#pragma unroll
        for (int qi = 0; qi < 8; qi++)
#pragma unroll
            for (int c = 0; c < WAY; c++) red[warp][qi][c] = acc[qi][c];
    __syncthreads();

    if (tid < 8 * WAY) {                        // 40 threads
        int qi = tid / WAY, c = tid % WAY;
        float s = 0.f;
#pragma unroll
        for (int w = 0; w < 8; w++) s += red[w][qi][c];
        atomicAdd(&g_S2[c][q0 + qi], s);
    }
}

// ---------------------------------------------------------------------------
// K6: logits (proven)
// ---------------------------------------------------------------------------
__global__ void logits_kernel(float* __restrict__ out)
{
    int warp = (blockIdx.x * blockDim.x + threadIdx.x) >> 5;
    int lane = threadIdx.x & 31;
    if (warp >= NQ) return;
    const int q = warp;

    float s1[WAY] = {0.f, 0.f, 0.f, 0.f, 0.f};
    const float* qb = g_bar[NS + q];
    for (int k = lane; k < DD; k += 32) {
        float qv = qb[k];
#pragma unroll
        for (int c = 0; c < WAY; c++) s1[c] += g_sbarsum[c][k] * qv;
    }
#pragma unroll
    for (int o = 16; o; o >>= 1)
#pragma unroll
        for (int c = 0; c < WAY; c++)
            s1[c] += __shfl_xor_sync(0xFFFFFFFFu, s1[c], o);

    if (lane < WAY) {
        int c = lane;
        float cnt = (float)g_cls_cnt[c];
        out[q * WAY + c] = -2.f * (float)(FF * FF) + (4.f * s1[c] - 2.f * g_S2[c][q]) / cnt;
    }
}

// ---------------------------------------------------------------------------
extern "C" void kernel_launch(void* const* d_in, const int* in_sizes, int n_in,
                              void* d_out, int out_size)
{
    const float*     sg  = (const float*)d_in[0];
    const float*     sl  = (const float*)d_in[1];
    const long long* lab = (const long long*)d_in[2];
    const float*     qg  = (const float*)d_in[3];
    const float*     ql  = (const float*)d_in[4];
    float*           out = (float*)d_out;

    const int smem = 2 * FF * PITCH * 2;               // 43520 B (C aliases X)
    static bool attr_set = false;
    if (!attr_set) {
        cudaFuncSetAttribute(gram_kernel, cudaFuncAttributeMaxDynamicSharedMemorySize, smem);
        attr_set = true;
    }

    const int rows = NITEM * FF;
    normalize_kernel<<<(rows * 32 + 255) / 256, 256>>>(sg, sl, qg, ql);
    rowsum_kernel<<<NITEM, 256>>>();
    prep_kernel<<<1, 512>>>(lab);
    gram_kernel<<<dim3(NBLK, WAY + NQ), 256, smem>>>();   // 2050 CTAs
    dot_kernel<<<dim3(40, 25), 256>>>();                  // 1000 CTAs
    logits_kernel<<<(NQ * 32 + 255) / 256, 256>>>(out);
}